// round 3
// baseline (speedup 1.0000x reference)
#include <cuda_runtime.h>
#include <cuda_bf16.h>
#include <math.h>
#include <float.h>

// Problem constants
#define N_TOK  16384          // B*S
#define HID    1024
#define GV     640            // NUM_GROUPS*NUM_VARS
#define NV     320            // NUM_VARS
#define CVD    128            // CODEVECTOR_DIM / NUM_GROUPS
#define NBLK2  256            // epilogue grid

// Scratch (static device globals; no allocation allowed)
__device__ float g_logits[(size_t)N_TOK * GV];     // 40 MB
__device__ float g_partial[(size_t)NBLK2 * GV];    // 640 KB

// ---------------------------------------------------------------------------
// Kernel 1: g_logits[M,N] = A[M,K] * B[N,K]^T + bias, M=16384 N=640 K=1024
// 128x64x16 tiles, 256 threads, 8x4 per-thread, double-buffered smem.
// Writes directly to the g_logits device symbol (no host symbol lookup).
// ---------------------------------------------------------------------------
#define BM 128
#define BN 64
#define BK 16

__global__ __launch_bounds__(256, 2)
void sgemm_nt_kernel(const float* __restrict__ A,
                     const float* __restrict__ B,
                     const float* __restrict__ bias)
{
    __shared__ float As[2][BK][BM + 4];   // [k][m], padded
    __shared__ float Bs[2][BK][BN + 4];   // [k][n], padded

    const int tid = threadIdx.x;
    const int tx  = tid & 15;     // n direction (4 cols each)
    const int ty  = tid >> 4;     // m direction (8 rows each)
    const int m0  = blockIdx.y * BM;
    const int n0  = blockIdx.x * BN;

    // global load index precompute
    const int fa0 = tid;            // A float4 slot, q=0
    const int fa1 = tid + 256;      // q=1
    const int arow0 = fa0 >> 2, akq0 = fa0 & 3;
    const int arow1 = fa1 >> 2, akq1 = fa1 & 3;
    const int brow  = tid >> 2, bkq  = tid & 3;

    const float* Abase0 = A + (size_t)(m0 + arow0) * HID + akq0 * 4;
    const float* Abase1 = A + (size_t)(m0 + arow1) * HID + akq1 * 4;
    const float* Bbase  = B + (size_t)(n0 + brow) * HID + bkq * 4;

    float4 aR0, aR1, bR;

    // prologue: tile 0
    aR0 = *reinterpret_cast<const float4*>(Abase0);
    aR1 = *reinterpret_cast<const float4*>(Abase1);
    bR  = *reinterpret_cast<const float4*>(Bbase);
    {
        As[0][akq0*4+0][arow0] = aR0.x; As[0][akq0*4+1][arow0] = aR0.y;
        As[0][akq0*4+2][arow0] = aR0.z; As[0][akq0*4+3][arow0] = aR0.w;
        As[0][akq1*4+0][arow1] = aR1.x; As[0][akq1*4+1][arow1] = aR1.y;
        As[0][akq1*4+2][arow1] = aR1.z; As[0][akq1*4+3][arow1] = aR1.w;
        Bs[0][bkq*4+0][brow] = bR.x; Bs[0][bkq*4+1][brow] = bR.y;
        Bs[0][bkq*4+2][brow] = bR.z; Bs[0][bkq*4+3][brow] = bR.w;
    }
    __syncthreads();

    float acc[8][4];
#pragma unroll
    for (int i = 0; i < 8; i++)
#pragma unroll
        for (int j = 0; j < 4; j++) acc[i][j] = 0.f;

    float af[2][8], bf[2][4];

#define LOADFRAG(BUF, KI, SLOT) do {                                            \
        float4 _a0 = *reinterpret_cast<const float4*>(&As[BUF][KI][ty*8]);      \
        float4 _a1 = *reinterpret_cast<const float4*>(&As[BUF][KI][ty*8+4]);    \
        af[SLOT][0]=_a0.x; af[SLOT][1]=_a0.y; af[SLOT][2]=_a0.z; af[SLOT][3]=_a0.w; \
        af[SLOT][4]=_a1.x; af[SLOT][5]=_a1.y; af[SLOT][6]=_a1.z; af[SLOT][7]=_a1.w; \
        float4 _b  = *reinterpret_cast<const float4*>(&Bs[BUF][KI][tx*4]);      \
        bf[SLOT][0]=_b.x; bf[SLOT][1]=_b.y; bf[SLOT][2]=_b.z; bf[SLOT][3]=_b.w; \
    } while (0)

    LOADFRAG(0, 0, 0);

    int buf = 0;
#pragma unroll 1
    for (int kt = 0; kt < HID / BK; kt++) {
        const bool more = (kt < HID / BK - 1);
        if (more) {
            const int koff = (kt + 1) * BK;
            aR0 = *reinterpret_cast<const float4*>(Abase0 + koff);
            aR1 = *reinterpret_cast<const float4*>(Abase1 + koff);
            bR  = *reinterpret_cast<const float4*>(Bbase  + koff);
        }
#pragma unroll
        for (int k = 0; k < BK; k++) {
            const int cur = k & 1, nxt = cur ^ 1;
            if (k < BK - 1) LOADFRAG(buf, k + 1, nxt);
#pragma unroll
            for (int i = 0; i < 8; i++)
#pragma unroll
                for (int j = 0; j < 4; j++)
                    acc[i][j] = fmaf(af[cur][i], bf[cur][j], acc[i][j]);
        }
        if (more) {
            const int nb = buf ^ 1;
            As[nb][akq0*4+0][arow0] = aR0.x; As[nb][akq0*4+1][arow0] = aR0.y;
            As[nb][akq0*4+2][arow0] = aR0.z; As[nb][akq0*4+3][arow0] = aR0.w;
            As[nb][akq1*4+0][arow1] = aR1.x; As[nb][akq1*4+1][arow1] = aR1.y;
            As[nb][akq1*4+2][arow1] = aR1.z; As[nb][akq1*4+3][arow1] = aR1.w;
            Bs[nb][bkq*4+0][brow] = bR.x; Bs[nb][bkq*4+1][brow] = bR.y;
            Bs[nb][bkq*4+2][brow] = bR.z; Bs[nb][bkq*4+3][brow] = bR.w;
            __syncthreads();
            buf = nb;
            LOADFRAG(buf, 0, 0);
        }
    }

    // epilogue: add bias, store to logits scratch
    float bv[4];
#pragma unroll
    for (int j = 0; j < 4; j++) bv[j] = bias[n0 + tx*4 + j];
#pragma unroll
    for (int i = 0; i < 8; i++) {
        const size_t row = (size_t)(m0 + ty*8 + i);
        float4 o;
        o.x = acc[i][0] + bv[0];
        o.y = acc[i][1] + bv[1];
        o.z = acc[i][2] + bv[2];
        o.w = acc[i][3] + bv[3];
        *reinterpret_cast<float4*>(g_logits + row * GV + n0 + tx*4) = o;
    }
}

// ---------------------------------------------------------------------------
// Kernel 2: per-row gumbel argmax + gather + soft-softmax marginal partials.
// grid = NBLK2 blocks x 256 threads. Block b handles tokens b, b+NBLK2, ...
// Two 128-thread halves per block, one per group. Deterministic (no atomics).
// ---------------------------------------------------------------------------
__device__ __forceinline__ unsigned long long pack_key(float z, int v)
{
    unsigned int b = __float_as_uint(z);
    b = (b & 0x80000000u) ? ~b : (b | 0x80000000u);   // order-preserving map
    return ((unsigned long long)b << 32) | (unsigned int)(0xFFFFFFFFu - (unsigned)v);
}

__global__ __launch_bounds__(256)
void epilogue_kernel(const float* __restrict__ u,
                     const float* __restrict__ cv,
                     float* __restrict__ out)
{
    __shared__ float marg[GV];
    __shared__ float red_max[8];
    __shared__ float red_sum[8];
    __shared__ unsigned long long red_arg[8];

    const int tid  = threadIdx.x;
    const int half = tid >> 7;        // group
    const int tt   = tid & 127;
    const int wid  = tid >> 5;
    const int lane = tid & 31;
    const int base = half * 4;        // warp-scratch base for this half
    const bool has2 = (tt < 64);

    for (int j = tid; j < GV; j += 256) marg[j] = 0.f;
    __syncthreads();

    for (int tok = blockIdx.x; tok < N_TOK; tok += NBLK2) {
        const float* lrow = g_logits + (size_t)tok * GV + half * NV;
        const float* urow = u + ((size_t)tok * 2 + half) * NV;

        const float l0 = lrow[tt];
        const float l1 = lrow[tt + 128];
        const float l2 = has2 ? lrow[tt + 256] : -FLT_MAX;

        // gumbel-perturbed score z = l - log(-log(u)) ; accurate logs (flip safety)
        const float z0 = l0 - logf(-logf(urow[tt]));
        const float z1 = l1 - logf(-logf(urow[tt + 128]));
        const float z2 = has2 ? (l2 - logf(-logf(urow[tt + 256]))) : -FLT_MAX;

        // local argmax key (exact first-index tie-break) and local max
        unsigned long long key = pack_key(z0, tt);
        {
            unsigned long long k1 = pack_key(z1, tt + 128);
            if (k1 > key) key = k1;
            if (has2) { unsigned long long k2 = pack_key(z2, tt + 256); if (k2 > key) key = k2; }
        }
        float m = fmaxf(l0, l1);
        if (has2) m = fmaxf(m, l2);

#pragma unroll
        for (int o = 16; o > 0; o >>= 1) {
            m = fmaxf(m, __shfl_xor_sync(0xFFFFFFFFu, m, o));
            unsigned long long ok = __shfl_xor_sync(0xFFFFFFFFu, key, o);
            if (ok > key) key = ok;
        }
        if (lane == 0) { red_max[wid] = m; red_arg[wid] = key; }
        __syncthreads();

        m = fmaxf(fmaxf(red_max[base], red_max[base+1]),
                  fmaxf(red_max[base+2], red_max[base+3]));
        key = red_arg[base];
#pragma unroll
        for (int j = 1; j < 4; j++) if (red_arg[base+j] > key) key = red_arg[base+j];
        const int idx = (int)(0xFFFFFFFFu - (unsigned int)(key & 0xFFFFFFFFull));

        // soft softmax (no gumbel, no tau) for the perplexity marginal
        const float e0 = __expf(l0 - m);
        const float e1 = __expf(l1 - m);
        const float e2 = has2 ? __expf(l2 - m) : 0.f;
        float s = e0 + e1 + e2;
#pragma unroll
        for (int o = 16; o > 0; o >>= 1) s += __shfl_xor_sync(0xFFFFFFFFu, s, o);
        if (lane == 0) red_sum[wid] = s;
        __syncthreads();
        s = red_sum[base] + red_sum[base+1] + red_sum[base+2] + red_sum[base+3];
        const float inv = __fdividef(1.f, s);

        marg[half*NV + tt]        += e0 * inv;
        marg[half*NV + tt + 128]  += e1 * inv;
        if (has2) marg[half*NV + tt + 256] += e2 * inv;

        // output gather: out[tok, half*128 + tt] = cv[half*320 + idx][tt]
        out[(size_t)tok * 256 + half * 128 + tt] =
            cv[((size_t)(half * NV + idx)) * CVD + tt];

        __syncthreads();   // protect red_* scratch across loop iterations
    }

    for (int j = tid; j < GV; j += 256)
        g_partial[(size_t)blockIdx.x * GV + j] = marg[j];
}

// ---------------------------------------------------------------------------
// Kernel 3: deterministic reduce of partials -> perplexity scalar.
// ---------------------------------------------------------------------------
__global__ void perplex_kernel(float* __restrict__ out, int out_size)
{
    const int tid = threadIdx.x;   // 640 threads
    float s = 0.f;
    for (int b = 0; b < NBLK2; b++) s += g_partial[(size_t)b * GV + tid];
    const float m = s * (1.0f / (float)N_TOK);
    __shared__ float sm[GV];
    sm[tid] = m * logf(m + 1e-7f);
    __syncthreads();
    if (tid == 0) {
        float s0 = 0.f, s1 = 0.f;
        for (int v = 0; v < NV; v++) { s0 += sm[v]; s1 += sm[NV + v]; }
        const float perp = expf(-s0) + expf(-s1);
        if (out_size > N_TOK * 256) out[(size_t)N_TOK * 256] = perp;
    }
}

// ---------------------------------------------------------------------------
extern "C" void kernel_launch(void* const* d_in, const int* in_sizes, int n_in,
                              void* d_out, int out_size)
{
    const float* hs = (const float*)d_in[0];   // [16384,1024]
    const float* W  = (const float*)d_in[1];   // [640,1024]
    const float* b  = (const float*)d_in[2];   // [640]
    const float* cv = (const float*)d_in[3];   // [640,128]
    const float* gu = (const float*)d_in[4];   // [32768,320]
    float* out = (float*)d_out;

    dim3 g1(GV / BN, N_TOK / BM);   // (10, 128)
    sgemm_nt_kernel<<<g1, 256>>>(hs, W, b);
    epilogue_kernel<<<NBLK2, 256>>>(gu, cv, out);
    perplex_kernel<<<1, GV>>>(out, out_size);
}

// round 7
// speedup vs baseline: 1.0660x; 1.0660x over previous
#include <cuda_runtime.h>
#include <cuda_bf16.h>
#include <math.h>
#include <float.h>
#include <stdint.h>

// Problem constants
#define N_TOK  16384          // B*S
#define HID    1024
#define GV     640            // NUM_GROUPS*NUM_VARS
#define NV     320            // NUM_VARS
#define CVD    128            // CODEVECTOR_DIM / NUM_GROUPS

#define NWARPS_EP 2048        // epilogue: total warps (256 blocks x 8 warps)
#define ROWS_PER_WARP 16      // 32768 rows / 2048 warps

// Scratch (static device globals; no allocation allowed)
__device__ float g_logits[(size_t)N_TOK * GV];          // 40 MB
__device__ float g_partial[(size_t)NWARPS_EP * NV];     // 2.6 MB

// ===========================================================================
// TF32 helpers (legacy mma.sync path — works on plain sm_100 target)
// ===========================================================================
__device__ __forceinline__ void tf32_split1(float a, uint32_t& hi, uint32_t& lo) {
    uint32_t h;
    asm("cvt.rna.tf32.f32 %0, %1;" : "=r"(h) : "f"(a));
    float l = a - __uint_as_float(h);
    uint32_t lw;
    asm("cvt.rna.tf32.f32 %0, %1;" : "=r"(lw) : "f"(l));
    hi = h; lo = lw;
}

__device__ __forceinline__ void mma16n8k8(float c[4], const uint32_t a[4],
                                          const uint32_t b[2]) {
    asm volatile(
        "mma.sync.aligned.m16n8k8.row.col.f32.tf32.tf32.f32 "
        "{%0,%1,%2,%3}, {%4,%5,%6,%7}, {%8,%9}, {%0,%1,%2,%3};"
        : "+f"(c[0]), "+f"(c[1]), "+f"(c[2]), "+f"(c[3])
        : "r"(a[0]), "r"(a[1]), "r"(a[2]), "r"(a[3]), "r"(b[0]), "r"(b[1]));
}

// ===========================================================================
// Kernel 1: 3xTF32 GEMM via mma.sync.m16n8k8.
// logits[16384,640] = A[16384,1024] * B[640,1024]^T + bias
// Block tile 128x128, 8 warps (4 m x 2 n), warp tile 32x64.
// K chunks of 16, double-buffered smem; hi/lo split done in-register on fill.
// ===========================================================================
#define BM 128
#define BN 128
#define BK 16
#define AP (BK + 4)          // A row pitch (uints) = 20
#define BP (BN + 4)          // B row pitch (uints) = 132

#define SZ_A (BM * AP)                 // 2560 uints
#define SZ_B (BK * BP)                 // 2112 uints
#define OFF_AH 0
#define OFF_AL SZ_A
#define OFF_BH (2 * SZ_A)
#define OFF_BL (2 * SZ_A + SZ_B)
#define STAGE  (2 * SZ_A + 2 * SZ_B)   // 9344 uints = 37376 B
#define SMEM_GEMM (2 * STAGE * 4)      // 74752 B

__global__ __launch_bounds__(256)
void gemm_tf32_kernel(const float* __restrict__ A,
                      const float* __restrict__ B,
                      const float* __restrict__ bias)
{
    extern __shared__ uint32_t S[];

    const int tid  = threadIdx.x;
    const int wid  = tid >> 5;
    const int lane = tid & 31;
    const int gid  = lane >> 2;         // group id (0..7)
    const int tig  = lane & 3;          // thread in group (0..3)
    const int wm   = (wid & 3) * 32;    // warp m offset in block
    const int wn   = (wid >> 2) * 64;   // warp n offset in block
    const int n0   = blockIdx.x * BN;
    const int m0   = blockIdx.y * BM;

    // fill indices: 512 float4 slots per operand, 2 per thread
    const int r0 = tid >> 2,          kq0 = tid & 3;
    const int r1 = (tid + 256) >> 2,  kq1 = (tid + 256) & 3;

    const float* Ag0 = A + (size_t)(m0 + r0) * HID + kq0 * 4;
    const float* Ag1 = A + (size_t)(m0 + r1) * HID + kq1 * 4;
    const float* Bg0 = B + (size_t)(n0 + r0) * HID + kq0 * 4;
    const float* Bg1 = B + (size_t)(n0 + r1) * HID + kq1 * 4;

    float c[2][8][4];
#pragma unroll
    for (int mt = 0; mt < 2; mt++)
#pragma unroll
        for (int j = 0; j < 8; j++)
#pragma unroll
            for (int q = 0; q < 4; q++) c[mt][j][q] = 0.f;

    float4 av0, av1, bv0, bv1;

#define SPLIT_STORE(vec, base, off) do {                                   \
        uint32_t h0,l0,h1,l1,h2,l2,h3,l3;                                  \
        tf32_split1((vec).x, h0, l0); tf32_split1((vec).y, h1, l1);        \
        tf32_split1((vec).z, h2, l2); tf32_split1((vec).w, h3, l3);        \
        uint32_t* ph = base;                                               \
        ph[(off) + 0] = h0; ph[(off) + 1] = h1;                            \
        ph[(off) + 2] = h2; ph[(off) + 3] = h3;                            \
        uint32_t* pl = base + (SZ_A ? 0 : 0);                              \
        (void)pl;                                                          \
    } while (0)

    // prologue: fill stage 0
    {
        uint32_t* st = S;
        av0 = *reinterpret_cast<const float4*>(Ag0);
        av1 = *reinterpret_cast<const float4*>(Ag1);
        bv0 = *reinterpret_cast<const float4*>(Bg0);
        bv1 = *reinterpret_cast<const float4*>(Bg1);
        {
            uint32_t h, l;
            const float a4[4] = {av0.x, av0.y, av0.z, av0.w};
#pragma unroll
            for (int q = 0; q < 4; q++) {
                tf32_split1(a4[q], h, l);
                st[OFF_AH + r0 * AP + kq0 * 4 + q] = h;
                st[OFF_AL + r0 * AP + kq0 * 4 + q] = l;
            }
            const float a4b[4] = {av1.x, av1.y, av1.z, av1.w};
#pragma unroll
            for (int q = 0; q < 4; q++) {
                tf32_split1(a4b[q], h, l);
                st[OFF_AH + r1 * AP + kq1 * 4 + q] = h;
                st[OFF_AL + r1 * AP + kq1 * 4 + q] = l;
            }
            const float b4[4] = {bv0.x, bv0.y, bv0.z, bv0.w};
#pragma unroll
            for (int q = 0; q < 4; q++) {
                tf32_split1(b4[q], h, l);
                st[OFF_BH + (kq0 * 4 + q) * BP + r0] = h;
                st[OFF_BL + (kq0 * 4 + q) * BP + r0] = l;
            }
            const float b4b[4] = {bv1.x, bv1.y, bv1.z, bv1.w};
#pragma unroll
            for (int q = 0; q < 4; q++) {
                tf32_split1(b4b[q], h, l);
                st[OFF_BH + (kq1 * 4 + q) * BP + r1] = h;
                st[OFF_BL + (kq1 * 4 + q) * BP + r1] = l;
            }
        }
    }
    __syncthreads();

    int buf = 0;
#pragma unroll 1
    for (int chunk = 0; chunk < HID / BK; chunk++) {
        const bool more = (chunk < HID / BK - 1);
        if (more) {
            const int ko = (chunk + 1) * BK;
            av0 = *reinterpret_cast<const float4*>(Ag0 + ko);
            av1 = *reinterpret_cast<const float4*>(Ag1 + ko);
            bv0 = *reinterpret_cast<const float4*>(Bg0 + ko);
            bv1 = *reinterpret_cast<const float4*>(Bg1 + ko);
        }

        const uint32_t* AH = S + buf * STAGE + OFF_AH;
        const uint32_t* AL = S + buf * STAGE + OFF_AL;
        const uint32_t* BH = S + buf * STAGE + OFF_BH;
        const uint32_t* BL = S + buf * STAGE + OFF_BL;

#pragma unroll
        for (int ks = 0; ks < BK; ks += 8) {
            uint32_t aH[2][4], aL[2][4], bb[8][2];
            // A-hi fragments
#pragma unroll
            for (int mt = 0; mt < 2; mt++) {
                const int row = wm + mt * 16 + gid;
                aH[mt][0] = AH[row * AP + ks + tig];
                aH[mt][1] = AH[(row + 8) * AP + ks + tig];
                aH[mt][2] = AH[row * AP + ks + tig + 4];
                aH[mt][3] = AH[(row + 8) * AP + ks + tig + 4];
            }
            // B-hi fragments
#pragma unroll
            for (int j = 0; j < 8; j++) {
                const int col = wn + j * 8 + gid;
                bb[j][0] = BH[(ks + tig) * BP + col];
                bb[j][1] = BH[(ks + tig + 4) * BP + col];
            }
            // hh
#pragma unroll
            for (int mt = 0; mt < 2; mt++)
#pragma unroll
                for (int j = 0; j < 8; j++) mma16n8k8(c[mt][j], aH[mt], bb[j]);
            // A-lo fragments; lh (uses B-hi still live)
#pragma unroll
            for (int mt = 0; mt < 2; mt++) {
                const int row = wm + mt * 16 + gid;
                aL[mt][0] = AL[row * AP + ks + tig];
                aL[mt][1] = AL[(row + 8) * AP + ks + tig];
                aL[mt][2] = AL[row * AP + ks + tig + 4];
                aL[mt][3] = AL[(row + 8) * AP + ks + tig + 4];
            }
#pragma unroll
            for (int mt = 0; mt < 2; mt++)
#pragma unroll
                for (int j = 0; j < 8; j++) mma16n8k8(c[mt][j], aL[mt], bb[j]);
            // B-lo fragments overwrite; hl (uses A-hi still live)
#pragma unroll
            for (int j = 0; j < 8; j++) {
                const int col = wn + j * 8 + gid;
                bb[j][0] = BL[(ks + tig) * BP + col];
                bb[j][1] = BL[(ks + tig + 4) * BP + col];
            }
#pragma unroll
            for (int mt = 0; mt < 2; mt++)
#pragma unroll
                for (int j = 0; j < 8; j++) mma16n8k8(c[mt][j], aH[mt], bb[j]);
        }

        if (more) {
            uint32_t* st = S + (buf ^ 1) * STAGE;
            uint32_t h, l;
            const float a4[4] = {av0.x, av0.y, av0.z, av0.w};
#pragma unroll
            for (int q = 0; q < 4; q++) {
                tf32_split1(a4[q], h, l);
                st[OFF_AH + r0 * AP + kq0 * 4 + q] = h;
                st[OFF_AL + r0 * AP + kq0 * 4 + q] = l;
            }
            const float a4b[4] = {av1.x, av1.y, av1.z, av1.w};
#pragma unroll
            for (int q = 0; q < 4; q++) {
                tf32_split1(a4b[q], h, l);
                st[OFF_AH + r1 * AP + kq1 * 4 + q] = h;
                st[OFF_AL + r1 * AP + kq1 * 4 + q] = l;
            }
            const float b4[4] = {bv0.x, bv0.y, bv0.z, bv0.w};
#pragma unroll
            for (int q = 0; q < 4; q++) {
                tf32_split1(b4[q], h, l);
                st[OFF_BH + (kq0 * 4 + q) * BP + r0] = h;
                st[OFF_BL + (kq0 * 4 + q) * BP + r0] = l;
            }
            const float b4b[4] = {bv1.x, bv1.y, bv1.z, bv1.w};
#pragma unroll
            for (int q = 0; q < 4; q++) {
                tf32_split1(b4b[q], h, l);
                st[OFF_BH + (kq1 * 4 + q) * BP + r1] = h;
                st[OFF_BL + (kq1 * 4 + q) * BP + r1] = l;
            }
        }
        __syncthreads();
        buf ^= 1;
    }

    // epilogue: add bias, write logits
#pragma unroll
    for (int mt = 0; mt < 2; mt++) {
        const int row = m0 + wm + mt * 16 + gid;
#pragma unroll
        for (int j = 0; j < 8; j++) {
            const int col = n0 + wn + j * 8 + tig * 2;
            const float b0 = bias[col], b1 = bias[col + 1];
            float2 o0 = make_float2(c[mt][j][0] + b0, c[mt][j][1] + b1);
            float2 o1 = make_float2(c[mt][j][2] + b0, c[mt][j][3] + b1);
            *reinterpret_cast<float2*>(g_logits + (size_t)row * GV + col) = o0;
            *reinterpret_cast<float2*>(g_logits + (size_t)(row + 8) * GV + col) = o1;
        }
    }
}

// ===========================================================================
// Kernel 2: warp-per-row epilogue: gumbel argmax + gather + softmax marginal.
// 256 blocks x 256 threads = 2048 warps; warp w handles rows w, w+2048, ...
// Row r = tok*2 + g; group g = w & 1 (stride 2048 preserves parity).
// ===========================================================================
__device__ __forceinline__ unsigned long long pack_key(float z, int v)
{
    unsigned int b = __float_as_uint(z);
    b = (b & 0x80000000u) ? ~b : (b | 0x80000000u);   // order-preserving map
    return ((unsigned long long)b << 32) | (unsigned int)(0xFFFFFFFFu - (unsigned)v);
}

__global__ __launch_bounds__(256)
void epilogue_kernel(const float* __restrict__ u,
                     const float* __restrict__ cv,
                     float* __restrict__ out)
{
    const int lane = threadIdx.x & 31;
    const int w    = blockIdx.x * 8 + (threadIdx.x >> 5);   // 0..2047
    const int g    = w & 1;

    float marg[10];
#pragma unroll
    for (int i = 0; i < 10; i++) marg[i] = 0.f;

#pragma unroll 1
    for (int j = 0; j < ROWS_PER_WARP; j++) {
        const int r   = w + j * NWARPS_EP;
        const int tok = r >> 1;
        const float* lrow = g_logits + (size_t)tok * GV + g * NV;
        const float* urow = u + (size_t)r * NV;

        float l[10];
        unsigned long long key = 0;
        float m = -FLT_MAX;
#pragma unroll
        for (int i = 0; i < 10; i++) {
            const int v = lane + i * 32;
            const float li = lrow[v];
            // accurate logs: argmax flips are catastrophic
            const float zi = li - logf(-logf(urow[v]));
            const unsigned long long k = pack_key(zi, v);
            if (k > key) key = k;
            m = fmaxf(m, li);
            l[i] = li;
        }
#pragma unroll
        for (int o = 16; o > 0; o >>= 1) {
            m = fmaxf(m, __shfl_xor_sync(0xFFFFFFFFu, m, o));
            const unsigned long long ok = __shfl_xor_sync(0xFFFFFFFFu, key, o);
            if (ok > key) key = ok;
        }
        float e[10], s = 0.f;
#pragma unroll
        for (int i = 0; i < 10; i++) { e[i] = __expf(l[i] - m); s += e[i]; }
#pragma unroll
        for (int o = 16; o > 0; o >>= 1) s += __shfl_xor_sync(0xFFFFFFFFu, s, o);
        const float inv = __fdividef(1.f, s);
#pragma unroll
        for (int i = 0; i < 10; i++) marg[i] += e[i] * inv;

        const int idx = (int)(0xFFFFFFFFu - (unsigned int)(key & 0xFFFFFFFFull));
        const float4 vv = *reinterpret_cast<const float4*>(
            cv + ((size_t)(g * NV + idx)) * CVD + lane * 4);
        *reinterpret_cast<float4*>(out + (size_t)tok * 256 + g * CVD + lane * 4) = vv;
    }

#pragma unroll
    for (int i = 0; i < 10; i++)
        g_partial[(size_t)w * NV + lane + i * 32] = marg[i];
}

// ===========================================================================
// Kernel 3: deterministic reduce of partials -> perplexity scalar.
// ===========================================================================
__global__ void perplex_kernel(float* __restrict__ out, int out_size)
{
    const int tid = threadIdx.x;        // 640 threads: g = tid/NV, v = tid%NV
    const int g = tid >= NV;
    const int v = tid - g * NV;
    float s = 0.f;
#pragma unroll 4
    for (int w = 0; w < NWARPS_EP / 2; w++)
        s += g_partial[(size_t)(2 * w + g) * NV + v];
    const float m = s * (1.0f / (float)N_TOK);
    __shared__ float sm[GV];
    sm[tid] = m * logf(m + 1e-7f);
    __syncthreads();
    if (tid == 0) {
        float s0 = 0.f, s1 = 0.f;
        for (int i = 0; i < NV; i++) { s0 += sm[i]; s1 += sm[NV + i]; }
        const float perp = expf(-s0) + expf(-s1);
        if (out_size > N_TOK * 256) out[(size_t)N_TOK * 256] = perp;
    }
}

// ===========================================================================
extern "C" void kernel_launch(void* const* d_in, const int* in_sizes, int n_in,
                              void* d_out, int out_size)
{
    const float* hs = (const float*)d_in[0];   // [16384,1024]
    const float* W  = (const float*)d_in[1];   // [640,1024]
    const float* b  = (const float*)d_in[2];   // [640]
    const float* cv = (const float*)d_in[3];   // [640,128]
    const float* gu = (const float*)d_in[4];   // [32768,320]
    float* out = (float*)d_out;

    cudaFuncSetAttribute(gemm_tf32_kernel,
                         cudaFuncAttributeMaxDynamicSharedMemorySize, SMEM_GEMM);

    gemm_tf32_kernel<<<dim3(GV / BN, N_TOK / BM), 256, SMEM_GEMM>>>(hs, W, b);
    epilogue_kernel<<<256, 256>>>(gu, cv, out);
    perplex_kernel<<<1, GV>>>(out, out_size);
}

// round 10
// speedup vs baseline: 1.8254x; 1.7123x over previous
#include <cuda_runtime.h>
#include <cuda_fp16.h>
#include <math.h>
#include <float.h>
#include <stdint.h>

// Problem constants
#define N_TOK  16384          // B*S
#define HID    1024
#define GV     640            // NUM_GROUPS*NUM_VARS
#define NV     320            // NUM_VARS
#define CVD    128            // CODEVECTOR_DIM / NUM_GROUPS

#define NWARPS_EP 2048        // epilogue: total warps (256 blocks x 8 warps)
#define ROWS_PER_WARP 16      // 32768 rows / 2048 warps

// Scratch (static device globals; no allocation allowed)
__device__ float g_logits[(size_t)N_TOK * GV];          // 40 MB
__device__ float g_partial[(size_t)NWARPS_EP * NV];     // 2.6 MB
__device__ float g_marg[GV];

// ===========================================================================
// FP16 3-term split GEMM via mma.sync.m16n8k16 (plain sm_100-legal).
// logits[16384,640] = A[16384,1024] * B[640,1024]^T + bias
// B pre-scaled by 2^12 (exact) to keep splits in fp16 normal range.
// Block tile 128x128, 8 warps (4m x 2n), warp tile 32x64. BK=16, 2 stages.
// smem: hi/lo interleaved as uint2 (one LDS.64 fetches both terms).
// ===========================================================================
#define BM 128
#define BN 128
#define BK 16
#define AP2 12      // A row pitch in uint2 (8 data + 4 pad) — conflict-free
#define BP2 132     // B row pitch in uint2 — conflict-free
#define SZ_A2 (BM * AP2)        // 1536 uint2
#define SZ_B2 (8 * BP2)         // 1056 uint2
#define STAGE2 (SZ_A2 + SZ_B2)  // 2592 uint2 = 20736 B

#define B_SCALE   4096.0f
#define B_UNSCALE (1.0f / 4096.0f)

__device__ __forceinline__ uint32_t pack_h2(__half lo, __half hi) {
    __half2 p = __halves2half2(lo, hi);   // lo -> bits[0:16]
    return *reinterpret_cast<uint32_t*>(&p);
}

// split float pair (x=k even, y=k odd) into {hi2, lo2} uint2
__device__ __forceinline__ uint2 split2(float x, float y) {
    __half hx = __float2half_rn(x), hy = __float2half_rn(y);
    float rx = x - __half2float(hx), ry = y - __half2float(hy);
    uint2 d;
    d.x = pack_h2(hx, hy);
    d.y = pack_h2(__float2half_rn(rx), __float2half_rn(ry));
    return d;
}

__device__ __forceinline__ void mma_f16(float c[4], const uint32_t a[4],
                                        const uint32_t b[2]) {
    asm volatile(
        "mma.sync.aligned.m16n8k16.row.col.f32.f16.f16.f32 "
        "{%0,%1,%2,%3}, {%4,%5,%6,%7}, {%8,%9}, {%0,%1,%2,%3};"
        : "+f"(c[0]), "+f"(c[1]), "+f"(c[2]), "+f"(c[3])
        : "r"(a[0]), "r"(a[1]), "r"(a[2]), "r"(a[3]), "r"(b[0]), "r"(b[1]));
}

__global__ __launch_bounds__(256, 2)
void gemm_f16x3_kernel(const float* __restrict__ A,
                       const float* __restrict__ B,
                       const float* __restrict__ bias)
{
    __shared__ uint2 S2[2][STAGE2];

    const int tid  = threadIdx.x;
    const int wid  = tid >> 5;
    const int lane = tid & 31;
    const int gid  = lane >> 2;         // 0..7
    const int tig  = lane & 3;          // 0..3
    const int wm   = (wid & 3) * 32;
    const int wn   = (wid >> 2) * 64;
    const int n0   = blockIdx.x * BN;
    const int m0   = blockIdx.y * BM;

    // fill indices: 512 float4 per operand per chunk, 2 per thread
    const int r0 = tid >> 2,         kq0 = tid & 3;
    const int r1 = r0 + 64,          kq1 = kq0;

    const float* Ag0 = A + (size_t)(m0 + r0) * HID + kq0 * 4;
    const float* Ag1 = A + (size_t)(m0 + r1) * HID + kq1 * 4;
    const float* Bg0 = B + (size_t)(n0 + r0) * HID + kq0 * 4;
    const float* Bg1 = B + (size_t)(n0 + r1) * HID + kq1 * 4;

    float c[2][8][4];
#pragma unroll
    for (int mt = 0; mt < 2; mt++)
#pragma unroll
        for (int j = 0; j < 8; j++)
#pragma unroll
            for (int q = 0; q < 4; q++) c[mt][j][q] = 0.f;

    float4 av0, av1, bv0, bv1;

#define FILL_STAGE(ST) do {                                                   \
        uint2* SA = S2[ST];                                                   \
        uint2* SB = S2[ST] + SZ_A2;                                           \
        SA[r0 * AP2 + 2*kq0    ] = split2(av0.x, av0.y);                      \
        SA[r0 * AP2 + 2*kq0 + 1] = split2(av0.z, av0.w);                      \
        SA[r1 * AP2 + 2*kq1    ] = split2(av1.x, av1.y);                      \
        SA[r1 * AP2 + 2*kq1 + 1] = split2(av1.z, av1.w);                      \
        SB[(2*kq0    ) * BP2 + r0] = split2(bv0.x * B_SCALE, bv0.y * B_SCALE);\
        SB[(2*kq0 + 1) * BP2 + r0] = split2(bv0.z * B_SCALE, bv0.w * B_SCALE);\
        SB[(2*kq1    ) * BP2 + r1] = split2(bv1.x * B_SCALE, bv1.y * B_SCALE);\
        SB[(2*kq1 + 1) * BP2 + r1] = split2(bv1.z * B_SCALE, bv1.w * B_SCALE);\
    } while (0)

    // prologue: load + fill stage 0
    av0 = *reinterpret_cast<const float4*>(Ag0);
    av1 = *reinterpret_cast<const float4*>(Ag1);
    bv0 = *reinterpret_cast<const float4*>(Bg0);
    bv1 = *reinterpret_cast<const float4*>(Bg1);
    FILL_STAGE(0);
    __syncthreads();

    int buf = 0;
#pragma unroll 1
    for (int chunk = 0; chunk < HID / BK; chunk++) {
        const bool more = (chunk < HID / BK - 1);
        if (more) {
            const int ko = (chunk + 1) * BK;
            av0 = *reinterpret_cast<const float4*>(Ag0 + ko);
            av1 = *reinterpret_cast<const float4*>(Ag1 + ko);
            bv0 = *reinterpret_cast<const float4*>(Bg0 + ko);
            bv1 = *reinterpret_cast<const float4*>(Bg1 + ko);
        }

        const uint2* SA = S2[buf];
        const uint2* SB = S2[buf] + SZ_A2;

        // A fragments (hi+lo in one LDS.64 each)
        uint32_t aH[2][4], aL[2][4];
#pragma unroll
        for (int mt = 0; mt < 2; mt++) {
            const int row = wm + mt * 16 + gid;
            const uint2 p0 = SA[row * AP2 + tig];
            const uint2 p1 = SA[(row + 8) * AP2 + tig];
            const uint2 p2 = SA[row * AP2 + tig + 4];
            const uint2 p3 = SA[(row + 8) * AP2 + tig + 4];
            aH[mt][0] = p0.x; aH[mt][1] = p1.x; aH[mt][2] = p2.x; aH[mt][3] = p3.x;
            aL[mt][0] = p0.y; aL[mt][1] = p1.y; aL[mt][2] = p2.y; aL[mt][3] = p3.y;
        }

#pragma unroll
        for (int jh = 0; jh < 2; jh++) {
            uint32_t bH[4][2], bL[4][2];
#pragma unroll
            for (int j4 = 0; j4 < 4; j4++) {
                const int col = wn + (jh * 4 + j4) * 8 + gid;
                const uint2 q0 = SB[tig * BP2 + col];
                const uint2 q1 = SB[(tig + 4) * BP2 + col];
                bH[j4][0] = q0.x; bH[j4][1] = q1.x;
                bL[j4][0] = q0.y; bL[j4][1] = q1.y;
            }
#pragma unroll
            for (int mt = 0; mt < 2; mt++)
#pragma unroll
                for (int j4 = 0; j4 < 4; j4++) {
                    float* cc = c[mt][jh * 4 + j4];
                    mma_f16(cc, aH[mt], bH[j4]);   // hh
                    mma_f16(cc, aL[mt], bH[j4]);   // lh
                    mma_f16(cc, aH[mt], bL[j4]);   // hl
                }
        }

        if (more) FILL_STAGE(buf ^ 1);
        __syncthreads();
        buf ^= 1;
    }

    // epilogue: unscale, add bias, write logits
#pragma unroll
    for (int mt = 0; mt < 2; mt++) {
        const int row = m0 + wm + mt * 16 + gid;
#pragma unroll
        for (int j = 0; j < 8; j++) {
            const int col = n0 + wn + j * 8 + tig * 2;
            const float b0 = bias[col], b1 = bias[col + 1];
            float2 o0 = make_float2(fmaf(c[mt][j][0], B_UNSCALE, b0),
                                    fmaf(c[mt][j][1], B_UNSCALE, b1));
            float2 o1 = make_float2(fmaf(c[mt][j][2], B_UNSCALE, b0),
                                    fmaf(c[mt][j][3], B_UNSCALE, b1));
            *reinterpret_cast<float2*>(g_logits + (size_t)row * GV + col) = o0;
            *reinterpret_cast<float2*>(g_logits + (size_t)(row + 8) * GV + col) = o1;
        }
    }
}

// ===========================================================================
// Kernel 2: warp-per-row epilogue: gumbel argmax + gather + softmax marginal.
// 256 blocks x 256 threads = 2048 warps; warp w handles rows w, w+2048, ...
// ===========================================================================
__device__ __forceinline__ unsigned long long pack_key(float z, int v)
{
    unsigned int b = __float_as_uint(z);
    b = (b & 0x80000000u) ? ~b : (b | 0x80000000u);   // order-preserving map
    return ((unsigned long long)b << 32) | (unsigned int)(0xFFFFFFFFu - (unsigned)v);
}

__global__ __launch_bounds__(256)
void epilogue_kernel(const float* __restrict__ u,
                     const float* __restrict__ cv,
                     float* __restrict__ out)
{
    const int lane = threadIdx.x & 31;
    const int w    = blockIdx.x * 8 + (threadIdx.x >> 5);   // 0..2047
    const int g    = w & 1;

    float marg[10];
#pragma unroll
    for (int i = 0; i < 10; i++) marg[i] = 0.f;

#pragma unroll 1
    for (int j = 0; j < ROWS_PER_WARP; j++) {
        const int r   = w + j * NWARPS_EP;
        const int tok = r >> 1;
        const float* lrow = g_logits + (size_t)tok * GV + g * NV;
        const float* urow = u + (size_t)r * NV;

        float l[10];
        unsigned long long key = 0;
        float m = -FLT_MAX;
#pragma unroll
        for (int i = 0; i < 10; i++) {
            const int v = lane + i * 32;
            const float li = lrow[v];
            // accurate logs: argmax flips are catastrophic
            const float zi = li - logf(-logf(urow[v]));
            const unsigned long long k = pack_key(zi, v);
            if (k > key) key = k;
            m = fmaxf(m, li);
            l[i] = li;
        }
#pragma unroll
        for (int o = 16; o > 0; o >>= 1) {
            m = fmaxf(m, __shfl_xor_sync(0xFFFFFFFFu, m, o));
            const unsigned long long ok = __shfl_xor_sync(0xFFFFFFFFu, key, o);
            if (ok > key) key = ok;
        }
        float e[10], s = 0.f;
#pragma unroll
        for (int i = 0; i < 10; i++) { e[i] = __expf(l[i] - m); s += e[i]; }
#pragma unroll
        for (int o = 16; o > 0; o >>= 1) s += __shfl_xor_sync(0xFFFFFFFFu, s, o);
        const float inv = __fdividef(1.f, s);
#pragma unroll
        for (int i = 0; i < 10; i++) marg[i] += e[i] * inv;

        const int idx = (int)(0xFFFFFFFFu - (unsigned int)(key & 0xFFFFFFFFull));
        const float4 vv = *reinterpret_cast<const float4*>(
            cv + ((size_t)(g * NV + idx)) * CVD + lane * 4);
        *reinterpret_cast<float4*>(out + (size_t)tok * 256 + g * CVD + lane * 4) = vv;
    }

#pragma unroll
    for (int i = 0; i < 10; i++)
        g_partial[(size_t)w * NV + lane + i * 32] = marg[i];
}

// ===========================================================================
// Kernel 3a: parallel deterministic reduce of partials -> marginal[640].
// grid 640 blocks x 256 threads; block b handles one (g,v) column.
// ===========================================================================
__global__ void reduce_marg_kernel()
{
    const int b = blockIdx.x;           // 0..639 -> j = g*NV + v
    const int g = b / NV;
    const int v = b - g * NV;
    const int t = threadIdx.x;

    float s = 0.f;
#pragma unroll
    for (int k = 0; k < 4; k++) {
        const int w = g + 2 * (t + 256 * k);
        s += g_partial[(size_t)w * NV + v];
    }
    __shared__ float red[256];
    red[t] = s;
    __syncthreads();
#pragma unroll
    for (int o = 128; o > 0; o >>= 1) {
        if (t < o) red[t] += red[t + o];
        __syncthreads();
    }
    if (t == 0) g_marg[b] = red[0] * (1.0f / (float)N_TOK);
}

// ===========================================================================
// Kernel 3b: finalize perplexity scalar.
// ===========================================================================
__global__ void perplex_kernel(float* __restrict__ out, int out_size)
{
    const int tid = threadIdx.x;   // 640 threads
    __shared__ float sm[GV];
    const float m = g_marg[tid];
    sm[tid] = m * logf(m + 1e-7f);
    __syncthreads();
    if (tid == 0) {
        float s0 = 0.f, s1 = 0.f;
        for (int i = 0; i < NV; i++) { s0 += sm[i]; s1 += sm[NV + i]; }
        const float perp = expf(-s0) + expf(-s1);
        if (out_size > N_TOK * 256) out[(size_t)N_TOK * 256] = perp;
    }
}

// ===========================================================================
extern "C" void kernel_launch(void* const* d_in, const int* in_sizes, int n_in,
                              void* d_out, int out_size)
{
    const float* hs = (const float*)d_in[0];   // [16384,1024]
    const float* W  = (const float*)d_in[1];   // [640,1024]
    const float* b  = (const float*)d_in[2];   // [640]
    const float* cv = (const float*)d_in[3];   // [640,128]
    const float* gu = (const float*)d_in[4];   // [32768,320]
    float* out = (float*)d_out;

    gemm_f16x3_kernel<<<dim3(GV / BN, N_TOK / BM), 256>>>(hs, W, b);
    epilogue_kernel<<<256, 256>>>(gu, cv, out);
    reduce_marg_kernel<<<GV, 256>>>();
    perplex_kernel<<<1, GV>>>(out, out_size);
}

// round 11
// speedup vs baseline: 1.9951x; 1.0930x over previous
#include <cuda_runtime.h>
#include <cuda_fp16.h>
#include <math.h>
#include <float.h>
#include <stdint.h>

// Problem constants
#define N_TOK  16384          // B*S
#define HID    1024
#define GV     640            // NUM_GROUPS*NUM_VARS
#define NV     320            // NUM_VARS
#define CVD    128            // CODEVECTOR_DIM / NUM_GROUPS
#define KP     (HID / 2)      // 512 k-pairs

#define NWARPS_EP 2048        // epilogue: total warps (256 blocks x 8 warps)
#define ROWS_PER_WARP 16      // 32768 rows / 2048 warps

// Scratch (static device globals; no allocation allowed)
__device__ float g_logits[(size_t)N_TOK * GV];          // 40 MB
__device__ float g_partial[(size_t)NWARPS_EP * NV];     // 2.6 MB
__device__ float g_marg[GV];
__device__ uint2 g_Ai[(size_t)N_TOK * KP];              // 64 MB: [row][kp] {hi2,lo2}
__device__ uint2 g_Bt[(size_t)KP * GV];                 // 2.5 MB: [kp][n]  {hi2,lo2}, x4096

#define B_SCALE   4096.0f
#define B_UNSCALE (1.0f / 4096.0f)

// ===========================================================================
// split helpers
// ===========================================================================
__device__ __forceinline__ uint32_t pack_h2(__half lo, __half hi) {
    __half2 p = __halves2half2(lo, hi);   // lo -> bits[0:16]
    return *reinterpret_cast<uint32_t*>(&p);
}
// split float pair (x=k even, y=k odd) into {hi2, lo2} uint2
__device__ __forceinline__ uint2 split2(float x, float y) {
    __half hx = __float2half_rn(x), hy = __float2half_rn(y);
    float rx = x - __half2float(hx), ry = y - __half2float(hy);
    uint2 d;
    d.x = pack_h2(hx, hy);
    d.y = pack_h2(__float2half_rn(rx), __float2half_rn(ry));
    return d;
}

// ===========================================================================
// Kernel 0: pre-split A -> g_Ai ([row][kp]) and B*4096 -> g_Bt ([kp][n]).
// One pair per thread.
// ===========================================================================
#define A_PAIRS ((size_t)N_TOK * KP)     // 8388608
#define B_PAIRS ((size_t)KP * GV)        // 327680
#define PS_THREADS 256

__global__ void presplit_kernel(const float* __restrict__ A,
                                const float* __restrict__ B)
{
    const size_t i = (size_t)blockIdx.x * PS_THREADS + threadIdx.x;
    if (i < A_PAIRS) {
        const float2 v = *reinterpret_cast<const float2*>(A + 2 * i);
        g_Ai[i] = split2(v.x, v.y);
    } else if (i < A_PAIRS + B_PAIRS) {
        const size_t i2 = i - A_PAIRS;       // = kp*GV + n  (write-coalesced)
        const int n  = (int)(i2 % GV);
        const int kp = (int)(i2 / GV);
        const float2 v = *reinterpret_cast<const float2*>(B + (size_t)n * HID + 2 * kp);
        g_Bt[i2] = split2(v.x * B_SCALE, v.y * B_SCALE);
    }
}

// ===========================================================================
// Kernel 1: FP16 3-term split GEMM via mma.sync.m16n8k16, cp.async fills.
// logits[16384,640] = A[16384,1024] * B[640,1024]^T + bias
// Block tile 128x128, 8 warps (4m x 2n), warp tile 32x64. BK=16, 2 stages.
// ===========================================================================
#define BM 128
#define BN 128
#define BK 16
#define AP2 12      // A row pitch in uint2 (8 data + 4 pad)
#define BP2 132     // B kp-row pitch in uint2
#define SZ_A2 (BM * AP2)        // 1536 uint2
#define SZ_B2 (8 * BP2)         // 1056 uint2
#define STAGE2 (SZ_A2 + SZ_B2)  // 2592 uint2 = 20736 B

__device__ __forceinline__ void mma_f16(float c[4], const uint32_t a[4],
                                        const uint32_t b[2]) {
    asm volatile(
        "mma.sync.aligned.m16n8k16.row.col.f32.f16.f16.f32 "
        "{%0,%1,%2,%3}, {%4,%5,%6,%7}, {%8,%9}, {%0,%1,%2,%3};"
        : "+f"(c[0]), "+f"(c[1]), "+f"(c[2]), "+f"(c[3])
        : "r"(a[0]), "r"(a[1]), "r"(a[2]), "r"(a[3]), "r"(b[0]), "r"(b[1]));
}

#define CP16(dst32, src) \
    asm volatile("cp.async.cg.shared.global [%0], [%1], 16;" \
                 :: "r"(dst32), "l"(src))
#define CP_COMMIT() asm volatile("cp.async.commit_group;" ::: "memory")
#define CP_WAIT1()  asm volatile("cp.async.wait_group 1;" ::: "memory")
#define CP_WAIT0()  asm volatile("cp.async.wait_group 0;" ::: "memory")

__global__ __launch_bounds__(256, 2)
void gemm_f16x3_kernel(const float* __restrict__ bias)
{
    __shared__ uint2 S2[2][STAGE2];

    const int tid  = threadIdx.x;
    const int wid  = tid >> 5;
    const int lane = tid & 31;
    const int gid  = lane >> 2;         // 0..7
    const int tig  = lane & 3;          // 0..3
    const int wm   = (wid & 3) * 32;
    const int wn   = (wid >> 2) * 64;
    const int n0   = blockIdx.x * BN;
    const int m0   = blockIdx.y * BM;

    // cp.async slot geometry (16B chunks)
    // A: 512 chunks/tile: row = c>>2 (0..127), jq = c&3 (16B within 64B row)
    const int arow0 = tid >> 2, ajq = tid & 3;
    const int arow1 = arow0 + 64;
    // B: 512 chunks/tile: kp-local = c>>6 (0..7), npos = c&63
    const int kpl0 = tid >> 6, npos = tid & 63;
    const int kpl1 = kpl0 + 4;

    // smem byte addresses for the 4 dst slots, per stage
    uint32_t sb[2];
    {
        uint32_t a;
        asm("{ .reg .u64 t; cvta.to.shared.u64 t, %1; cvt.u32.u64 %0, t; }"
            : "=r"(a) : "l"((const void*)&S2[0][0]));
        sb[0] = a;
        sb[1] = a + STAGE2 * 8;
    }
    const uint32_t dA0_off = (uint32_t)(arow0 * AP2 + ajq * 2) * 8;
    const uint32_t dA1_off = (uint32_t)(arow1 * AP2 + ajq * 2) * 8;
    const uint32_t dB0_off = (uint32_t)(SZ_A2 + kpl0 * BP2 + npos * 2) * 8;
    const uint32_t dB1_off = (uint32_t)(SZ_A2 + kpl1 * BP2 + npos * 2) * 8;

    const uint2* Asrc0 = g_Ai + (size_t)(m0 + arow0) * KP + ajq * 2;
    const uint2* Asrc1 = g_Ai + (size_t)(m0 + arow1) * KP + ajq * 2;
    const uint2* Bsrc0 = g_Bt + (size_t)kpl0 * GV + n0 + npos * 2;
    const uint2* Bsrc1 = g_Bt + (size_t)kpl1 * GV + n0 + npos * 2;

#define ISSUE(CH, ST) do {                                                   \
        CP16(sb[ST] + dA0_off, Asrc0 + (CH) * 8);                            \
        CP16(sb[ST] + dA1_off, Asrc1 + (CH) * 8);                            \
        CP16(sb[ST] + dB0_off, Bsrc0 + (size_t)(CH) * 8 * GV);               \
        CP16(sb[ST] + dB1_off, Bsrc1 + (size_t)(CH) * 8 * GV);               \
    } while (0)

    float c[2][8][4];
#pragma unroll
    for (int mt = 0; mt < 2; mt++)
#pragma unroll
        for (int j = 0; j < 8; j++)
#pragma unroll
            for (int q = 0; q < 4; q++) c[mt][j][q] = 0.f;

    // prologue
    ISSUE(0, 0);
    CP_COMMIT();

    int buf = 0;
#pragma unroll 1
    for (int chunk = 0; chunk < HID / BK; chunk++) {
        const bool more = (chunk < HID / BK - 1);
        if (more) {
            ISSUE(chunk + 1, buf ^ 1);
            CP_COMMIT();
            CP_WAIT1();
        } else {
            CP_WAIT0();
        }
        __syncthreads();

        const uint2* SA = S2[buf];
        const uint2* SB = S2[buf] + SZ_A2;

        // A fragments (hi+lo in one LDS.64 each)
        uint32_t aH[2][4], aL[2][4];
#pragma unroll
        for (int mt = 0; mt < 2; mt++) {
            const int row = wm + mt * 16 + gid;
            const uint2 p0 = SA[row * AP2 + tig];
            const uint2 p1 = SA[(row + 8) * AP2 + tig];
            const uint2 p2 = SA[row * AP2 + tig + 4];
            const uint2 p3 = SA[(row + 8) * AP2 + tig + 4];
            aH[mt][0] = p0.x; aH[mt][1] = p1.x; aH[mt][2] = p2.x; aH[mt][3] = p3.x;
            aL[mt][0] = p0.y; aL[mt][1] = p1.y; aL[mt][2] = p2.y; aL[mt][3] = p3.y;
        }

#pragma unroll
        for (int jh = 0; jh < 2; jh++) {
            uint32_t bH[4][2], bL[4][2];
#pragma unroll
            for (int j4 = 0; j4 < 4; j4++) {
                const int col = wn + (jh * 4 + j4) * 8 + gid;
                const uint2 q0 = SB[tig * BP2 + col];
                const uint2 q1 = SB[(tig + 4) * BP2 + col];
                bH[j4][0] = q0.x; bH[j4][1] = q1.x;
                bL[j4][0] = q0.y; bL[j4][1] = q1.y;
            }
#pragma unroll
            for (int mt = 0; mt < 2; mt++)
#pragma unroll
                for (int j4 = 0; j4 < 4; j4++) {
                    float* cc = c[mt][jh * 4 + j4];
                    mma_f16(cc, aH[mt], bH[j4]);   // hh
                    mma_f16(cc, aL[mt], bH[j4]);   // lh
                    mma_f16(cc, aH[mt], bL[j4]);   // hl
                }
        }

        __syncthreads();   // all warps done with S2[buf] before it is refilled
        buf ^= 1;
    }

    // epilogue: unscale, add bias, write logits
#pragma unroll
    for (int mt = 0; mt < 2; mt++) {
        const int row = m0 + wm + mt * 16 + gid;
#pragma unroll
        for (int j = 0; j < 8; j++) {
            const int col = n0 + wn + j * 8 + tig * 2;
            const float b0 = bias[col], b1 = bias[col + 1];
            float2 o0 = make_float2(fmaf(c[mt][j][0], B_UNSCALE, b0),
                                    fmaf(c[mt][j][1], B_UNSCALE, b1));
            float2 o1 = make_float2(fmaf(c[mt][j][2], B_UNSCALE, b0),
                                    fmaf(c[mt][j][3], B_UNSCALE, b1));
            *reinterpret_cast<float2*>(g_logits + (size_t)row * GV + col) = o0;
            *reinterpret_cast<float2*>(g_logits + (size_t)(row + 8) * GV + col) = o1;
        }
    }
}

// ===========================================================================
// Kernel 2: warp-per-row epilogue: gumbel argmax + gather + softmax marginal.
// ===========================================================================
__device__ __forceinline__ unsigned long long pack_key(float z, int v)
{
    unsigned int b = __float_as_uint(z);
    b = (b & 0x80000000u) ? ~b : (b | 0x80000000u);   // order-preserving map
    return ((unsigned long long)b << 32) | (unsigned int)(0xFFFFFFFFu - (unsigned)v);
}

__global__ __launch_bounds__(256)
void epilogue_kernel(const float* __restrict__ u,
                     const float* __restrict__ cv,
                     float* __restrict__ out)
{
    const int lane = threadIdx.x & 31;
    const int w    = blockIdx.x * 8 + (threadIdx.x >> 5);   // 0..2047
    const int g    = w & 1;

    float marg[10];
#pragma unroll
    for (int i = 0; i < 10; i++) marg[i] = 0.f;

#pragma unroll 1
    for (int j = 0; j < ROWS_PER_WARP; j++) {
        const int r   = w + j * NWARPS_EP;
        const int tok = r >> 1;
        const float* lrow = g_logits + (size_t)tok * GV + g * NV;
        const float* urow = u + (size_t)r * NV;

        float l[10];
        unsigned long long key = 0;
        float m = -FLT_MAX;
#pragma unroll
        for (int i = 0; i < 10; i++) {
            const int v = lane + i * 32;
            const float li = lrow[v];
            // accurate logs: argmax flips are catastrophic
            const float zi = li - logf(-logf(urow[v]));
            const unsigned long long k = pack_key(zi, v);
            if (k > key) key = k;
            m = fmaxf(m, li);
            l[i] = li;
        }
#pragma unroll
        for (int o = 16; o > 0; o >>= 1) {
            m = fmaxf(m, __shfl_xor_sync(0xFFFFFFFFu, m, o));
            const unsigned long long ok = __shfl_xor_sync(0xFFFFFFFFu, key, o);
            if (ok > key) key = ok;
        }
        float e[10], s = 0.f;
#pragma unroll
        for (int i = 0; i < 10; i++) { e[i] = __expf(l[i] - m); s += e[i]; }
#pragma unroll
        for (int o = 16; o > 0; o >>= 1) s += __shfl_xor_sync(0xFFFFFFFFu, s, o);
        const float inv = __fdividef(1.f, s);
#pragma unroll
        for (int i = 0; i < 10; i++) marg[i] += e[i] * inv;

        const int idx = (int)(0xFFFFFFFFu - (unsigned int)(key & 0xFFFFFFFFull));
        const float4 vv = *reinterpret_cast<const float4*>(
            cv + ((size_t)(g * NV + idx)) * CVD + lane * 4);
        *reinterpret_cast<float4*>(out + (size_t)tok * 256 + g * CVD + lane * 4) = vv;
    }

#pragma unroll
    for (int i = 0; i < 10; i++)
        g_partial[(size_t)w * NV + lane + i * 32] = marg[i];
}

// ===========================================================================
// Kernel 3a: parallel deterministic reduce of partials -> marginal[640].
// ===========================================================================
__global__ void reduce_marg_kernel()
{
    const int b = blockIdx.x;           // 0..639 -> j = g*NV + v
    const int g = b / NV;
    const int v = b - g * NV;
    const int t = threadIdx.x;

    float s = 0.f;
#pragma unroll
    for (int k = 0; k < 4; k++) {
        const int w = g + 2 * (t + 256 * k);
        s += g_partial[(size_t)w * NV + v];
    }
    __shared__ float red[256];
    red[t] = s;
    __syncthreads();
#pragma unroll
    for (int o = 128; o > 0; o >>= 1) {
        if (t < o) red[t] += red[t + o];
        __syncthreads();
    }
    if (t == 0) g_marg[b] = red[0] * (1.0f / (float)N_TOK);
}

// ===========================================================================
// Kernel 3b: finalize perplexity scalar.
// ===========================================================================
__global__ void perplex_kernel(float* __restrict__ out, int out_size)
{
    const int tid = threadIdx.x;   // 640 threads
    __shared__ float sm[GV];
    const float m = g_marg[tid];
    sm[tid] = m * logf(m + 1e-7f);
    __syncthreads();
    if (tid == 0) {
        float s0 = 0.f, s1 = 0.f;
        for (int i = 0; i < NV; i++) { s0 += sm[i]; s1 += sm[NV + i]; }
        const float perp = expf(-s0) + expf(-s1);
        if (out_size > N_TOK * 256) out[(size_t)N_TOK * 256] = perp;
    }
}

// ===========================================================================
extern "C" void kernel_launch(void* const* d_in, const int* in_sizes, int n_in,
                              void* d_out, int out_size)
{
    const float* hs = (const float*)d_in[0];   // [16384,1024]
    const float* W  = (const float*)d_in[1];   // [640,1024]
    const float* b  = (const float*)d_in[2];   // [640]
    const float* cv = (const float*)d_in[3];   // [640,128]
    const float* gu = (const float*)d_in[4];   // [32768,320]
    float* out = (float*)d_out;

    const int ps_blocks = (int)((A_PAIRS + B_PAIRS + PS_THREADS - 1) / PS_THREADS);
    presplit_kernel<<<ps_blocks, PS_THREADS>>>(hs, W);
    gemm_f16x3_kernel<<<dim3(GV / BN, N_TOK / BM), 256>>>(b);
    epilogue_kernel<<<256, 256>>>(gu, cv, out);
    reduce_marg_kernel<<<GV, 256>>>();
    perplex_kernel<<<1, GV>>>(out, out_size);
}

// round 12
// speedup vs baseline: 2.0545x; 1.0298x over previous
#include <cuda_runtime.h>
#include <cuda_fp16.h>
#include <math.h>
#include <float.h>
#include <stdint.h>

// Problem constants
#define N_TOK  16384          // B*S
#define HID    1024
#define GV     640            // NUM_GROUPS*NUM_VARS
#define NV     320            // NUM_VARS
#define CVD    128            // CODEVECTOR_DIM / NUM_GROUPS
#define KP     (HID / 2)      // 512 k-pairs

#define NWARPS_EP 4096        // epilogue: total warps (512 blocks x 8 warps)
#define ROWS_PER_WARP 8       // 32768 rows / 4096 warps

// Scratch (static device globals; no allocation allowed)
__device__ float g_logits[(size_t)N_TOK * GV];          // 40 MB
__device__ float g_partial[(size_t)NWARPS_EP * NV];     // 5.2 MB
__device__ float g_marg[GV];
__device__ uint2 g_Ai[(size_t)N_TOK * KP];              // 64 MB: [row][kp] {hi2,lo2}
__device__ uint2 g_Bt[(size_t)KP * GV];                 // 2.5 MB: [kp][n]  {hi2,lo2}, x4096

#define B_SCALE   4096.0f
#define B_UNSCALE (1.0f / 4096.0f)

// ===========================================================================
// split helpers
// ===========================================================================
__device__ __forceinline__ uint32_t pack_h2(__half lo, __half hi) {
    __half2 p = __halves2half2(lo, hi);   // lo -> bits[0:16]
    return *reinterpret_cast<uint32_t*>(&p);
}
// split float pair (x=k even, y=k odd) into {hi2, lo2} uint2
__device__ __forceinline__ uint2 split2(float x, float y) {
    __half hx = __float2half_rn(x), hy = __float2half_rn(y);
    float rx = x - __half2float(hx), ry = y - __half2float(hy);
    uint2 d;
    d.x = pack_h2(hx, hy);
    d.y = pack_h2(__float2half_rn(rx), __float2half_rn(ry));
    return d;
}

// ===========================================================================
// Kernel 0: pre-split A -> g_Ai ([row][kp]) and B*4096 -> g_Bt ([kp][n]).
// ===========================================================================
#define A_PAIRS ((size_t)N_TOK * KP)     // 8388608
#define B_PAIRS ((size_t)KP * GV)        // 327680
#define PS_THREADS 256

__global__ void presplit_kernel(const float* __restrict__ A,
                                const float* __restrict__ B)
{
    const size_t i = (size_t)blockIdx.x * PS_THREADS + threadIdx.x;
    if (i < A_PAIRS) {
        const float2 v = *reinterpret_cast<const float2*>(A + 2 * i);
        g_Ai[i] = split2(v.x, v.y);
    } else if (i < A_PAIRS + B_PAIRS) {
        const size_t i2 = i - A_PAIRS;       // = kp*GV + n  (write-coalesced)
        const int n  = (int)(i2 % GV);
        const int kp = (int)(i2 / GV);
        const float2 v = *reinterpret_cast<const float2*>(B + (size_t)n * HID + 2 * kp);
        g_Bt[i2] = split2(v.x * B_SCALE, v.y * B_SCALE);
    }
}

// ===========================================================================
// Kernel 1: FP16 3-term split GEMM via mma.sync.m16n8k16, cp.async fills.
// Block tile 128x64, 8 warps (4m x 2n), warp tile 32x32. BK=16, 2 stages.
// 1280 CTAs, 3 CTAs/SM.
// ===========================================================================
#define BM 128
#define BN 64
#define BK 16
#define AP2 12      // A row pitch in uint2 (8 data + 4 pad)
#define BP2 68      // B kp-row pitch in uint2 (64 + 4 pad)
#define SZ_A2 (BM * AP2)        // 1536 uint2
#define SZ_B2 (8 * BP2)         // 544 uint2
#define STAGE2 (SZ_A2 + SZ_B2)  // 2080 uint2 = 16640 B

__device__ __forceinline__ void mma_f16(float c[4], const uint32_t a[4],
                                        const uint32_t b[2]) {
    asm volatile(
        "mma.sync.aligned.m16n8k16.row.col.f32.f16.f16.f32 "
        "{%0,%1,%2,%3}, {%4,%5,%6,%7}, {%8,%9}, {%0,%1,%2,%3};"
        : "+f"(c[0]), "+f"(c[1]), "+f"(c[2]), "+f"(c[3])
        : "r"(a[0]), "r"(a[1]), "r"(a[2]), "r"(a[3]), "r"(b[0]), "r"(b[1]));
}

#define CP16(dst32, src) \
    asm volatile("cp.async.cg.shared.global [%0], [%1], 16;" \
                 :: "r"(dst32), "l"(src))
#define CP_COMMIT() asm volatile("cp.async.commit_group;" ::: "memory")
#define CP_WAIT1()  asm volatile("cp.async.wait_group 1;" ::: "memory")
#define CP_WAIT0()  asm volatile("cp.async.wait_group 0;" ::: "memory")

__global__ __launch_bounds__(256, 3)
void gemm_f16x3_kernel(const float* __restrict__ bias)
{
    __shared__ uint2 S2[2][STAGE2];

    const int tid  = threadIdx.x;
    const int wid  = tid >> 5;
    const int lane = tid & 31;
    const int gid  = lane >> 2;         // 0..7
    const int tig  = lane & 3;          // 0..3
    const int wm   = (wid & 3) * 32;    // 4 m-warps
    const int wn   = (wid >> 2) * 32;   // 2 n-warps
    const int n0   = blockIdx.x * BN;
    const int m0   = blockIdx.y * BM;

    // cp.async slot geometry (16B chunks): A 512 slots, B 256 slots, 3/thread
    const int arow0 = tid >> 2, ajq = tid & 3;
    const int arow1 = arow0 + 64;
    const int kpl = tid >> 5, npos = tid & 31;   // B: kp-local 0..7, 16B pos 0..31

    uint32_t sb[2];
    {
        uint32_t a;
        asm("{ .reg .u64 t; cvta.to.shared.u64 t, %1; cvt.u32.u64 %0, t; }"
            : "=r"(a) : "l"((const void*)&S2[0][0]));
        sb[0] = a;
        sb[1] = a + STAGE2 * 8;
    }
    const uint32_t dA0_off = (uint32_t)(arow0 * AP2 + ajq * 2) * 8;
    const uint32_t dA1_off = (uint32_t)(arow1 * AP2 + ajq * 2) * 8;
    const uint32_t dB_off  = (uint32_t)(SZ_A2 + kpl * BP2 + npos * 2) * 8;

    const uint2* Asrc0 = g_Ai + (size_t)(m0 + arow0) * KP + ajq * 2;
    const uint2* Asrc1 = g_Ai + (size_t)(m0 + arow1) * KP + ajq * 2;
    const uint2* Bsrc  = g_Bt + (size_t)kpl * GV + n0 + npos * 2;

#define ISSUE(CH, ST) do {                                                   \
        CP16(sb[ST] + dA0_off, Asrc0 + (CH) * 8);                            \
        CP16(sb[ST] + dA1_off, Asrc1 + (CH) * 8);                            \
        CP16(sb[ST] + dB_off,  Bsrc  + (size_t)(CH) * 8 * GV);               \
    } while (0)

    float c[2][4][4];
#pragma unroll
    for (int mt = 0; mt < 2; mt++)
#pragma unroll
        for (int j = 0; j < 4; j++)
#pragma unroll
            for (int q = 0; q < 4; q++) c[mt][j][q] = 0.f;

    // prologue
    ISSUE(0, 0);
    CP_COMMIT();

    int buf = 0;
#pragma unroll 1
    for (int chunk = 0; chunk < HID / BK; chunk++) {
        const bool more = (chunk < HID / BK - 1);
        if (more) {
            ISSUE(chunk + 1, buf ^ 1);
            CP_COMMIT();
            CP_WAIT1();
        } else {
            CP_WAIT0();
        }
        __syncthreads();

        const uint2* SA = S2[buf];
        const uint2* SB = S2[buf] + SZ_A2;

        // A fragments (hi+lo in one LDS.64 each)
        uint32_t aH[2][4], aL[2][4];
#pragma unroll
        for (int mt = 0; mt < 2; mt++) {
            const int row = wm + mt * 16 + gid;
            const uint2 p0 = SA[row * AP2 + tig];
            const uint2 p1 = SA[(row + 8) * AP2 + tig];
            const uint2 p2 = SA[row * AP2 + tig + 4];
            const uint2 p3 = SA[(row + 8) * AP2 + tig + 4];
            aH[mt][0] = p0.x; aH[mt][1] = p1.x; aH[mt][2] = p2.x; aH[mt][3] = p3.x;
            aL[mt][0] = p0.y; aL[mt][1] = p1.y; aL[mt][2] = p2.y; aL[mt][3] = p3.y;
        }

        uint32_t bH[4][2], bL[4][2];
#pragma unroll
        for (int j4 = 0; j4 < 4; j4++) {
            const int col = wn + j4 * 8 + gid;
            const uint2 q0 = SB[tig * BP2 + col];
            const uint2 q1 = SB[(tig + 4) * BP2 + col];
            bH[j4][0] = q0.x; bH[j4][1] = q1.x;
            bL[j4][0] = q0.y; bL[j4][1] = q1.y;
        }
#pragma unroll
        for (int mt = 0; mt < 2; mt++)
#pragma unroll
            for (int j4 = 0; j4 < 4; j4++) {
                float* cc = c[mt][j4];
                mma_f16(cc, aH[mt], bH[j4]);   // hh
                mma_f16(cc, aL[mt], bH[j4]);   // lh
                mma_f16(cc, aH[mt], bL[j4]);   // hl
            }

        __syncthreads();   // all warps done with S2[buf] before it is refilled
        buf ^= 1;
    }

    // epilogue: unscale, add bias, write logits
#pragma unroll
    for (int mt = 0; mt < 2; mt++) {
        const int row = m0 + wm + mt * 16 + gid;
#pragma unroll
        for (int j = 0; j < 4; j++) {
            const int col = n0 + wn + j * 8 + tig * 2;
            const float b0 = bias[col], b1 = bias[col + 1];
            float2 o0 = make_float2(fmaf(c[mt][j][0], B_UNSCALE, b0),
                                    fmaf(c[mt][j][1], B_UNSCALE, b1));
            float2 o1 = make_float2(fmaf(c[mt][j][2], B_UNSCALE, b0),
                                    fmaf(c[mt][j][3], B_UNSCALE, b1));
            *reinterpret_cast<float2*>(g_logits + (size_t)row * GV + col) = o0;
            *reinterpret_cast<float2*>(g_logits + (size_t)(row + 8) * GV + col) = o1;
        }
    }
}

// ===========================================================================
// Kernel 2: warp-per-row epilogue: gumbel argmax + gather + softmax marginal.
// 512 blocks x 256 threads = 4096 warps; warp w handles rows w, w+4096, ...
// ===========================================================================
__device__ __forceinline__ unsigned long long pack_key(float z, int v)
{
    unsigned int b = __float_as_uint(z);
    b = (b & 0x80000000u) ? ~b : (b | 0x80000000u);   // order-preserving map
    return ((unsigned long long)b << 32) | (unsigned int)(0xFFFFFFFFu - (unsigned)v);
}

__global__ __launch_bounds__(256)
void epilogue_kernel(const float* __restrict__ u,
                     const float* __restrict__ cv,
                     float* __restrict__ out)
{
    const int lane = threadIdx.x & 31;
    const int w    = blockIdx.x * 8 + (threadIdx.x >> 5);   // 0..4095
    const int g    = w & 1;

    float marg[10];
#pragma unroll
    for (int i = 0; i < 10; i++) marg[i] = 0.f;

#pragma unroll 1
    for (int j = 0; j < ROWS_PER_WARP; j++) {
        const int r   = w + j * NWARPS_EP;
        const int tok = r >> 1;
        const float* lrow = g_logits + (size_t)tok * GV + g * NV;
        const float* urow = u + (size_t)r * NV;

        float l[10];
        unsigned long long key = 0;
        float m = -FLT_MAX;
#pragma unroll
        for (int i = 0; i < 10; i++) {
            const int v = lane + i * 32;
            const float li = lrow[v];
            // accurate logs: argmax flips are catastrophic
            const float zi = li - logf(-logf(urow[v]));
            const unsigned long long k = pack_key(zi, v);
            if (k > key) key = k;
            m = fmaxf(m, li);
            l[i] = li;
        }
#pragma unroll
        for (int o = 16; o > 0; o >>= 1) {
            m = fmaxf(m, __shfl_xor_sync(0xFFFFFFFFu, m, o));
            const unsigned long long ok = __shfl_xor_sync(0xFFFFFFFFu, key, o);
            if (ok > key) key = ok;
        }
        float e[10], s = 0.f;
#pragma unroll
        for (int i = 0; i < 10; i++) { e[i] = __expf(l[i] - m); s += e[i]; }
#pragma unroll
        for (int o = 16; o > 0; o >>= 1) s += __shfl_xor_sync(0xFFFFFFFFu, s, o);
        const float inv = __fdividef(1.f, s);
#pragma unroll
        for (int i = 0; i < 10; i++) marg[i] += e[i] * inv;

        const int idx = (int)(0xFFFFFFFFu - (unsigned int)(key & 0xFFFFFFFFull));
        const float4 vv = *reinterpret_cast<const float4*>(
            cv + ((size_t)(g * NV + idx)) * CVD + lane * 4);
        *reinterpret_cast<float4*>(out + (size_t)tok * 256 + g * CVD + lane * 4) = vv;
    }

#pragma unroll
    for (int i = 0; i < 10; i++)
        g_partial[(size_t)w * NV + lane + i * 32] = marg[i];
}

// ===========================================================================
// Kernel 3a: parallel deterministic reduce of partials -> marginal[640].
// ===========================================================================
__global__ void reduce_marg_kernel()
{
    const int b = blockIdx.x;           // 0..639 -> j = g*NV + v
    const int g = b / NV;
    const int v = b - g * NV;
    const int t = threadIdx.x;

    float s = 0.f;
#pragma unroll
    for (int k = 0; k < 8; k++) {
        const int w = g + 2 * (t + 256 * k);
        s += g_partial[(size_t)w * NV + v];
    }
    __shared__ float red[256];
    red[t] = s;
    __syncthreads();
#pragma unroll
    for (int o = 128; o > 0; o >>= 1) {
        if (t < o) red[t] += red[t + o];
        __syncthreads();
    }
    if (t == 0) g_marg[b] = red[0] * (1.0f / (float)N_TOK);
}

// ===========================================================================
// Kernel 3b: finalize perplexity scalar.
// ===========================================================================
__global__ void perplex_kernel(float* __restrict__ out, int out_size)
{
    const int tid = threadIdx.x;   // 640 threads
    __shared__ float sm[GV];
    const float m = g_marg[tid];
    sm[tid] = m * logf(m + 1e-7f);
    __syncthreads();
    if (tid == 0) {
        float s0 = 0.f, s1 = 0.f;
        for (int i = 0; i < NV; i++) { s0 += sm[i]; s1 += sm[NV + i]; }
        const float perp = expf(-s0) + expf(-s1);
        if (out_size > N_TOK * 256) out[(size_t)N_TOK * 256] = perp;
    }
}

// ===========================================================================
extern "C" void kernel_launch(void* const* d_in, const int* in_sizes, int n_in,
                              void* d_out, int out_size)
{
    const float* hs = (const float*)d_in[0];   // [16384,1024]
    const float* W  = (const float*)d_in[1];   // [640,1024]
    const float* b  = (const float*)d_in[2];   // [640]
    const float* cv = (const float*)d_in[3];   // [640,128]
    const float* gu = (const float*)d_in[4];   // [32768,320]
    float* out = (float*)d_out;

    const int ps_blocks = (int)((A_PAIRS + B_PAIRS + PS_THREADS - 1) / PS_THREADS);
    presplit_kernel<<<ps_blocks, PS_THREADS>>>(hs, W);
    gemm_f16x3_kernel<<<dim3(GV / BN, N_TOK / BM), 256>>>(b);
    epilogue_kernel<<<512, 256>>>(gu, cv, out);
    reduce_marg_kernel<<<GV, 256>>>();
    perplex_kernel<<<1, GV>>>(out, out_size);
}